// round 2
// baseline (speedup 1.0000x reference)
#include <cuda_runtime.h>
#include <math.h>

#define BATCH 16
#define HH 1024
#define WW 1024
#define NPIX (HH*WW)
#define NTOT (BATCH*NPIX)

#define TILE 64
#define TILE_PX (TILE*TILE)          // 4096
#define TILES_X (WW/TILE)            // 16
#define TILES_TOT (NTOT/TILE_PX)     // 4096
#define TPB1 256
#define VPT (TILE_PX/4/TPB1)         // 4 float4 loads per thread

// Scratch (allocation-free: __device__ globals)
__device__ int g_parP[NTOT];
__device__ int g_parT[NTOT];
__device__ unsigned char g_fg[NTOT];     // bit0: pred>0.5, bit1: target>0
__device__ unsigned char g_flagP[NTOT];
__device__ unsigned char g_flagT[NTOT];
__device__ double g_sum;

// ---------------------------------------------------------------------------
// union-find primitives
// ---------------------------------------------------------------------------
__device__ __forceinline__ int lfind(volatile int* par, int l) {
    int p = par[l];
    while (p != l) { l = p; p = par[l]; }
    return l;
}
__device__ __forceinline__ void lunite(int* par, int a, int b) {
    while (true) {
        a = lfind(par, a);
        b = lfind(par, b);
        if (a == b) return;
        if (a < b) { int t = a; a = b; b = t; }
        int old = atomicMin(&par[a], b);
        if (old == a) return;
        a = old;
    }
}
__device__ __forceinline__ int gfind(int* par, int l) {
    int p = *((volatile int*)&par[l]);
    while (p != l) { l = p; p = *((volatile int*)&par[l]); }
    return l;
}
__device__ __forceinline__ void gunite(int* par, int a, int b) {
    while (true) {
        a = gfind(par, a);
        b = gfind(par, b);
        if (a == b) return;
        if (a < b) { int t = a; a = b; b = t; }
        int old = atomicMin(&par[a], b);
        if (old == a) return;
        a = old;
    }
}

// ---------------------------------------------------------------------------
// k_local: fused init + tile-local CCL (64x64 tile in shared memory)
// ---------------------------------------------------------------------------
__global__ __launch_bounds__(TPB1) void k_local(const float* __restrict__ preds,
                                                const float* __restrict__ targs) {
    __shared__ int sparP[TILE_PX];
    __shared__ int sparT[TILE_PX];
    __shared__ unsigned char sfg[TILE_PX];

    const int tile = blockIdx.x;
    const int tx = tile & (TILES_X - 1);
    const int ty = tile / TILES_X;             // 0..255 (global tile row)
    const int gx0 = tx * TILE;
    const int gy0 = ty * TILE;

    // ---- load + init (vectorized) ----
#pragma unroll
    for (int k = 0; k < VPT; k++) {
        int l4 = threadIdx.x + k * TPB1;       // 0..1023
        int lbase = l4 << 2;
        int ly = lbase >> 6;
        int lx = lbase & 63;
        int g = (gy0 + ly) * WW + gx0 + lx;
        int g4 = g >> 2;
        float4 p = reinterpret_cast<const float4*>(preds)[g4];
        float4 t = reinterpret_cast<const float4*>(targs)[g4];
        uchar4 f;
        f.x = (p.x > 0.5f ? 1 : 0) | (t.x > 0.0f ? 2 : 0);
        f.y = (p.y > 0.5f ? 1 : 0) | (t.y > 0.0f ? 2 : 0);
        f.z = (p.z > 0.5f ? 1 : 0) | (t.z > 0.0f ? 2 : 0);
        f.w = (p.w > 0.5f ? 1 : 0) | (t.w > 0.0f ? 2 : 0);
        reinterpret_cast<uchar4*>(g_fg)[g4] = f;
        reinterpret_cast<uchar4*>(g_flagP)[g4] = make_uchar4(0, 0, 0, 0);
        reinterpret_cast<uchar4*>(g_flagT)[g4] = make_uchar4(0, 0, 0, 0);
        sfg[lbase]     = f.x;
        sfg[lbase + 1] = f.y;
        sfg[lbase + 2] = f.z;
        sfg[lbase + 3] = f.w;
        sparP[lbase] = lbase;     sparT[lbase] = lbase;
        sparP[lbase + 1] = lbase + 1; sparT[lbase + 1] = lbase + 1;
        sparP[lbase + 2] = lbase + 2; sparT[lbase + 2] = lbase + 2;
        sparP[lbase + 3] = lbase + 3; sparT[lbase + 3] = lbase + 3;
    }
    if (blockIdx.x == 0 && threadIdx.x == 0) g_sum = 0.0;
    __syncthreads();

    // ---- local merge (left / up within tile) ----
#pragma unroll
    for (int k = 0; k < TILE_PX / TPB1; k++) {
        int l = threadIdx.x + k * TPB1;
        unsigned char f = sfg[l];
        if (!f) continue;
        int lx = l & 63;
        int ly = l >> 6;
        unsigned char fl = (lx > 0) ? sfg[l - 1] : 0;
        unsigned char fu = (ly > 0) ? sfg[l - TILE] : 0;
        if (f & 1) {
            if (fl & 1) lunite(sparP, l, l - 1);
            if (fu & 1) lunite(sparP, l, l - TILE);
        }
        if (f & 2) {
            if (fl & 2) lunite(sparT, l, l - 1);
            if (fu & 2) lunite(sparT, l, l - TILE);
        }
    }
    __syncthreads();

    // ---- compress locally, write global parents (fg only) ----
#pragma unroll
    for (int k = 0; k < TILE_PX / TPB1; k++) {
        int l = threadIdx.x + k * TPB1;
        unsigned char f = sfg[l];
        if (!f) continue;
        int g = (gy0 + (l >> 6)) * WW + gx0 + (l & 63);
        if (f & 1) {
            int r = lfind(sparP, l);
            g_parP[g] = (gy0 + (r >> 6)) * WW + gx0 + (r & 63);
        }
        if (f & 2) {
            int r = lfind(sparT, l);
            g_parT[g] = (gy0 + (r >> 6)) * WW + gx0 + (r & 63);
        }
    }
}

// ---------------------------------------------------------------------------
// k_boundary: union across tile edges only
// horizontal: rows y with y%64==0 && y%1024!=0 (merge up)   -> 240*1024 px
// vertical:   cols x with x%64==0 && x!=0     (merge left)  -> 15*16384 px
// ---------------------------------------------------------------------------
#define NHB (240*1024)
#define NVB (15*16384)
__global__ void k_boundary() {
    int i = blockIdx.x * blockDim.x + threadIdx.x;
    int g, n;
    if (i < NHB) {
        int r = i >> 10;            // 0..239
        int m = r / 15;             // image
        int rb = r % 15;
        int y = m * HH + (rb + 1) * TILE;
        int x = i & (WW - 1);
        g = y * WW + x;
        n = g - WW;                 // up
    } else if (i < NHB + NVB) {
        int j = i - NHB;
        int c = j >> 14;            // 0..14
        int y = j & (16384 - 1);
        int x = (c + 1) * TILE;
        g = y * WW + x;
        n = g - 1;                  // left
    } else {
        return;
    }
    unsigned char f = g_fg[g];
    if (!f) return;
    unsigned char fn = g_fg[n];
    if (f & fn & 1) gunite(g_parP, g, n);
    if (f & fn & 2) gunite(g_parT, g, n);
}

// ---------------------------------------------------------------------------
// k_compress_flag: par[i] <- root (write only if changed); mistakes flag root
// ---------------------------------------------------------------------------
__global__ void k_compress_flag() {
    int i = blockIdx.x * blockDim.x + threadIdx.x;
    if (i >= NTOT) return;
    unsigned char f = g_fg[i];
    if (!f) return;
    if (f & 1) {
        int r = gfind(g_parP, i);
        if (g_parP[i] != r) g_parP[i] = r;
        if (!(f & 2)) g_flagP[r] = 1;
    }
    if (f & 2) {
        int r = gfind(g_parT, i);
        if (g_parT[i] != r) g_parT[i] = r;
        if (!(f & 1)) g_flagT[r] = 1;
    }
}

// ---------------------------------------------------------------------------
// k_final: fused weighted BCE-with-logits + reduction
// weight = 0.5 + 0.25*negflag + 0.25*posflag
// ---------------------------------------------------------------------------
__global__ void k_final(const float* __restrict__ preds,
                        const float* __restrict__ targs) {
    int i = blockIdx.x * blockDim.x + threadIdx.x;   // vec4 index
    int base = i << 2;
    float local = 0.0f;
    if (base < NTOT) {
        float4 p4 = reinterpret_cast<const float4*>(preds)[i];
        float4 t4 = reinterpret_cast<const float4*>(targs)[i];
        float pv[4] = {p4.x, p4.y, p4.z, p4.w};
        float tv[4] = {t4.x, t4.y, t4.z, t4.w};
#pragma unroll
        for (int j = 0; j < 4; j++) {
            int idx = base + j;
            float p = pv[j];
            float t = tv[j];
            float loss = fmaxf(p, 0.0f) - p * t + log1pf(expf(-fabsf(p)));
            float w = 0.5f;
            if (t > 0.0f)  w += 0.25f * (float)g_flagT[g_parT[idx]];
            if (p > 0.5f)  w += 0.25f * (float)g_flagP[g_parP[idx]];
            local += w * loss;
        }
    }
#pragma unroll
    for (int off = 16; off > 0; off >>= 1)
        local += __shfl_down_sync(0xffffffffu, local, off);
    __shared__ float ssum[8];
    int lane = threadIdx.x & 31;
    int warp = threadIdx.x >> 5;
    if (lane == 0) ssum[warp] = local;
    __syncthreads();
    if (warp == 0) {
        float v = (lane < (blockDim.x >> 5)) ? ssum[lane] : 0.0f;
#pragma unroll
        for (int off = 4; off > 0; off >>= 1)
            v += __shfl_down_sync(0xffffffffu, v, off);
        if (lane == 0) atomicAdd(&g_sum, (double)v);
    }
}

__global__ void k_out(float* __restrict__ out) {
    out[0] = (float)(g_sum / (double)NTOT);
}

// ---------------------------------------------------------------------------
extern "C" void kernel_launch(void* const* d_in, const int* in_sizes, int n_in,
                              void* d_out, int out_size) {
    const float* preds = (const float*)d_in[0];
    const float* targs = (const float*)d_in[1];
    float* out = (float*)d_out;

    const int TPB = 256;
    k_local<<<TILES_TOT, TPB1>>>(preds, targs);
    k_boundary<<<(NHB + NVB + TPB - 1) / TPB, TPB>>>();
    k_compress_flag<<<(NTOT + TPB - 1) / TPB, TPB>>>();
    k_final<<<(NTOT / 4 + TPB - 1) / TPB, TPB>>>(preds, targs);
    k_out<<<1, 1>>>(out);
}

// round 3
// speedup vs baseline: 7.8386x; 7.8386x over previous
#include <cuda_runtime.h>
#include <math.h>

#define BATCH 16
#define HH 1024
#define WW 1024
#define NPIX (HH*WW)
#define NTOT (BATCH*NPIX)
#define NW   (NTOT/32)          // 524288 bitmap words
#define MASK31 0x7fffffff

// Scratch (__device__ globals; no allocation)
__device__ int g_parP[NTOT];
__device__ int g_parT[NTOT];
__device__ unsigned int g_bmP[NW];
__device__ unsigned int g_bmT[NW];
__device__ double g_sum;

// ---------------------------------------------------------------------------
// k_init: fg bitmaps + run-start parent init (one block = one 1024-px row)
// ---------------------------------------------------------------------------
__global__ __launch_bounds__(256) void k_init(const float* __restrict__ preds,
                                              const float* __restrict__ targs) {
    __shared__ unsigned char snP[256], snT[256];
    int t = threadIdx.x;
    int i4 = blockIdx.x * 256 + t;
    float4 p  = reinterpret_cast<const float4*>(preds)[i4];
    float4 tg = reinterpret_cast<const float4*>(targs)[i4];
    unsigned int nP = (unsigned int)(p.x  > 0.5f) | ((unsigned int)(p.y  > 0.5f) << 1)
                    | ((unsigned int)(p.z  > 0.5f) << 2) | ((unsigned int)(p.w  > 0.5f) << 3);
    unsigned int nT = (unsigned int)(tg.x > 0.0f) | ((unsigned int)(tg.y > 0.0f) << 1)
                    | ((unsigned int)(tg.z > 0.0f) << 2) | ((unsigned int)(tg.w > 0.0f) << 3);
    snP[t] = (unsigned char)nP;
    snT[t] = (unsigned char)nT;
    __syncthreads();

    int w = t >> 3;          // word within row (0..31)
    int b = t & 7;           // nibble group within word
    unsigned int wordP = 0, wordT = 0;
#pragma unroll
    for (int j = 0; j < 8; j++) {
        wordP |= ((unsigned int)snP[w * 8 + j]) << (4 * j);
        wordT |= ((unsigned int)snT[w * 8 + j]) << (4 * j);
    }
    if (b == 0) {
        g_bmP[blockIdx.x * 32 + w] = wordP;
        g_bmT[blockIdx.x * 32 + w] = wordT;
    }
    int basew = blockIdx.x * 1024 + w * 32;
    int4 pv, tv;
#pragma unroll
    for (int e = 0; e < 4; e++) {
        int k = 4 * b + e;
        unsigned int lowmask = (k == 0) ? 0u : ((1u << k) - 1u);
        unsigned int zp = (~wordP) & lowmask;
        unsigned int zt = (~wordT) & lowmask;
        int sp = zp ? (32 - __clz(zp)) : 0;   // run start within word
        int st = zt ? (32 - __clz(zt)) : 0;
        int vp = ((wordP >> k) & 1) ? (basew + sp) : (basew + k);
        int vt = ((wordT >> k) & 1) ? (basew + st) : (basew + k);
        reinterpret_cast<int*>(&pv)[e] = vp;
        reinterpret_cast<int*>(&tv)[e] = vt;
    }
    reinterpret_cast<int4*>(g_parP)[basew / 4 + b] = pv;
    reinterpret_cast<int4*>(g_parT)[basew / 4 + b] = tv;
    if (blockIdx.x == 0 && t == 0) g_sum = 0.0;
}

// ---------------------------------------------------------------------------
// union-find (merge phase: no plain-store compression; atomicMin linking)
// ---------------------------------------------------------------------------
__device__ __forceinline__ int find_nc(int* par, int l) {
    int p = par[l];
    while (p != l) { l = p; p = par[l]; }
    return l;
}
__device__ __forceinline__ void unite(int* par, int a, int b) {
    while (true) {
        a = find_nc(par, a);
        b = find_nc(par, b);
        if (a == b) return;
        if (a < b) { int tmp = a; a = b; b = tmp; }   // a > b
        int old = atomicMin(&par[a], b);
        if (old == a) return;
        a = old;
    }
}

// post-merge find with path halving (plain stores safe: no concurrent atomicMin;
// sign bit only ever lives on roots, halving writes only non-root entries)
__device__ __forceinline__ int find_h(int* par, int l) {
    int p = par[l] & MASK31;
    while (p != l) {
        int gp = par[p] & MASK31;
        par[l] = gp;
        l = gp;
        p = par[l] & MASK31;
    }
    return l;
}

// ---------------------------------------------------------------------------
// k_merge: cross-word horizontal links + one union per vertical overlap start
// ---------------------------------------------------------------------------
__global__ void k_merge() {
    int w = blockIdx.x * blockDim.x + threadIdx.x;
    if (w >= NW) return;
    int base = w * 32;
    unsigned int cP = g_bmP[w], cT = g_bmT[w];
    int wx = w & 31;
    if (wx > 0) {
        if ((cP & 1u) && (g_bmP[w - 1] >> 31)) unite(g_parP, base, base - 1);
        if ((cT & 1u) && (g_bmT[w - 1] >> 31)) unite(g_parT, base, base - 1);
    }
    int row = w >> 5;
    if (row & (HH - 1)) {                      // not first row of image
        unsigned int uP = g_bmP[w - 32], uT = g_bmT[w - 32];
        unsigned int o, s;
        o = cP & uP; s = o & ~(o << 1);
        while (s) { int k = __ffs(s) - 1; s &= s - 1; unite(g_parP, base + k, base + k - WW); }
        o = cT & uT; s = o & ~(o << 1);
        while (s) { int k = __ffs(s) - 1; s &= s - 1; unite(g_parT, base + k, base + k - WW); }
    }
}

// ---------------------------------------------------------------------------
// k_flag: one flag per run that contains >= 1 mistake pixel (sign bit on root)
// ---------------------------------------------------------------------------
__device__ __forceinline__ void flag_runs(int* par, unsigned int bm, unsigned int mistake, int base) {
    unsigned int runs = bm & ~(bm << 1);       // run starts within word
    while (runs) {
        int s = __ffs(runs) - 1; runs &= runs - 1;
        unsigned int rest = (~bm) & (s == 31 ? 0x80000000u : (~0u << s));
        int e = rest ? (__ffs(rest) - 1) : 32;
        unsigned int runmask = ((e < 32 ? ((1u << e) - 1u) : ~0u)) & (~0u << s);
        if (mistake & runmask) {
            int r = find_h(par, base + s);
            atomicOr(&par[r], (int)0x80000000);
        }
    }
}
__global__ void k_flag() {
    int w = blockIdx.x * blockDim.x + threadIdx.x;
    if (w >= NW) return;
    int base = w * 32;
    unsigned int bP = g_bmP[w], bT = g_bmT[w];
    flag_runs(g_parP, bP, bP & ~bT, base);     // pred component touches target-bg
    flag_runs(g_parT, bT, bT & ~bP, base);     // target component touches pred-bg
}

// ---------------------------------------------------------------------------
// k_final: fused weighted BCE-with-logits + reduction
// weight = 0.5 + 0.25*flagT(root) [t fg] + 0.25*flagP(root) [p fg]
// ---------------------------------------------------------------------------
__device__ __forceinline__ float rootflag(int* par, int l) {
    int p = par[l];
    int m = p & MASK31;
    while (m != l) {
        int p2 = par[m];
        int m2 = p2 & MASK31;
        if (m2 != m) par[l] = m2;   // halving (plain store of valid ancestor)
        l = m; p = p2; m = m2;
    }
    return (p < 0) ? 0.25f : 0.0f;
}

__global__ void k_final(const float* __restrict__ preds,
                        const float* __restrict__ targs) {
    int i = blockIdx.x * blockDim.x + threadIdx.x;   // vec4 index
    int base = i << 2;
    float local = 0.0f;
    float4 p4 = reinterpret_cast<const float4*>(preds)[i];
    float4 t4 = reinterpret_cast<const float4*>(targs)[i];
    float pv[4] = {p4.x, p4.y, p4.z, p4.w};
    float tv[4] = {t4.x, t4.y, t4.z, t4.w};
#pragma unroll
    for (int j = 0; j < 4; j++) {
        int idx = base + j;
        float p = pv[j];
        float t = tv[j];
        float loss = fmaxf(p, 0.0f) - p * t + log1pf(expf(-fabsf(p)));
        float w = 0.5f;
        if (t > 0.0f) w += rootflag(g_parT, idx);
        if (p > 0.5f) w += rootflag(g_parP, idx);
        local += w * loss;
    }
#pragma unroll
    for (int off = 16; off > 0; off >>= 1)
        local += __shfl_down_sync(0xffffffffu, local, off);
    __shared__ float ssum[8];
    int lane = threadIdx.x & 31;
    int warp = threadIdx.x >> 5;
    if (lane == 0) ssum[warp] = local;
    __syncthreads();
    if (warp == 0) {
        float v = (lane < (blockDim.x >> 5)) ? ssum[lane] : 0.0f;
#pragma unroll
        for (int off = 4; off > 0; off >>= 1)
            v += __shfl_down_sync(0xffffffffu, v, off);
        if (lane == 0) atomicAdd(&g_sum, (double)v);
    }
}

__global__ void k_out(float* __restrict__ out) {
    out[0] = (float)(g_sum / (double)NTOT);
}

// ---------------------------------------------------------------------------
extern "C" void kernel_launch(void* const* d_in, const int* in_sizes, int n_in,
                              void* d_out, int out_size) {
    const float* preds = (const float*)d_in[0];
    const float* targs = (const float*)d_in[1];
    float* out = (float*)d_out;

    k_init<<<NTOT / 1024, 256>>>(preds, targs);
    k_merge<<<NW / 256, 256>>>();
    k_flag<<<NW / 256, 256>>>();
    k_final<<<NTOT / 4 / 256, 256>>>(preds, targs);
    k_out<<<1, 1>>>(out);
}

// round 4
// speedup vs baseline: 10.6871x; 1.3634x over previous
#include <cuda_runtime.h>
#include <math.h>

#define BATCH 16
#define HH 1024
#define WW 1024
#define NPIX (HH*WW)
#define NTOT (BATCH*NPIX)
#define NW   (NTOT/32)          // 524288 bitmap words
#define MASK31 0x7fffffff

// Scratch (__device__ globals; no allocation)
__device__ int g_parP[NTOT];
__device__ int g_parT[NTOT];
__device__ unsigned int g_bmP[NW];
__device__ unsigned int g_bmT[NW];
__device__ unsigned int g_wP[NW];   // per-pixel component-flag bitmaps
__device__ unsigned int g_wT[NW];
__device__ double g_sum;

// ---------------------------------------------------------------------------
// k_init: fg bitmaps + run-start parent init (one block = one 1024-px row)
// ---------------------------------------------------------------------------
__global__ __launch_bounds__(256) void k_init(const float* __restrict__ preds,
                                              const float* __restrict__ targs) {
    __shared__ unsigned char snP[256], snT[256];
    int t = threadIdx.x;
    int i4 = blockIdx.x * 256 + t;
    float4 p  = reinterpret_cast<const float4*>(preds)[i4];
    float4 tg = reinterpret_cast<const float4*>(targs)[i4];
    unsigned int nP = (unsigned int)(p.x  > 0.5f) | ((unsigned int)(p.y  > 0.5f) << 1)
                    | ((unsigned int)(p.z  > 0.5f) << 2) | ((unsigned int)(p.w  > 0.5f) << 3);
    unsigned int nT = (unsigned int)(tg.x > 0.0f) | ((unsigned int)(tg.y > 0.0f) << 1)
                    | ((unsigned int)(tg.z > 0.0f) << 2) | ((unsigned int)(tg.w > 0.0f) << 3);
    snP[t] = (unsigned char)nP;
    snT[t] = (unsigned char)nT;
    __syncthreads();

    int w = t >> 3;          // word within row (0..31)
    int b = t & 7;           // nibble group within word
    unsigned int wordP = 0, wordT = 0;
#pragma unroll
    for (int j = 0; j < 8; j++) {
        wordP |= ((unsigned int)snP[w * 8 + j]) << (4 * j);
        wordT |= ((unsigned int)snT[w * 8 + j]) << (4 * j);
    }
    if (b == 0) {
        g_bmP[blockIdx.x * 32 + w] = wordP;
        g_bmT[blockIdx.x * 32 + w] = wordT;
    }
    int basew = blockIdx.x * 1024 + w * 32;
    int4 pv, tv;
#pragma unroll
    for (int e = 0; e < 4; e++) {
        int k = 4 * b + e;
        unsigned int lowmask = (k == 0) ? 0u : ((1u << k) - 1u);
        unsigned int zp = (~wordP) & lowmask;
        unsigned int zt = (~wordT) & lowmask;
        int sp = zp ? (32 - __clz(zp)) : 0;   // run start within word
        int st = zt ? (32 - __clz(zt)) : 0;
        int vp = ((wordP >> k) & 1) ? (basew + sp) : (basew + k);
        int vt = ((wordT >> k) & 1) ? (basew + st) : (basew + k);
        reinterpret_cast<int*>(&pv)[e] = vp;
        reinterpret_cast<int*>(&tv)[e] = vt;
    }
    reinterpret_cast<int4*>(g_parP)[basew / 4 + b] = pv;
    reinterpret_cast<int4*>(g_parT)[basew / 4 + b] = tv;
    if (blockIdx.x == 0 && t == 0) g_sum = 0.0;
}

// ---------------------------------------------------------------------------
// union-find (merge phase: atomicMin linking, no plain-store compression)
// ---------------------------------------------------------------------------
__device__ __forceinline__ int find_nc(int* par, int l) {
    int p = par[l];
    while (p != l) { l = p; p = par[l]; }
    return l;
}
__device__ __forceinline__ void unite(int* par, int a, int b) {
    while (true) {
        a = find_nc(par, a);
        b = find_nc(par, b);
        if (a == b) return;
        if (a < b) { int tmp = a; a = b; b = tmp; }   // a > b
        int old = atomicMin(&par[a], b);
        if (old == a) return;
        a = old;
    }
}

// post-merge find with path halving; returns root, sets *fl if root flagged.
// sign bit lives only on roots; halving writes only valid masked ancestors.
__device__ __forceinline__ int find_flag(int* par, int l, bool* fl) {
    int p = par[l];
    int m = p & MASK31;
    while (m != l) {
        int p2 = par[m];
        int m2 = p2 & MASK31;
        if (m2 != m) par[l] = m2;
        l = m; p = p2; m = m2;
    }
    *fl = (p < 0);
    return l;
}

// ---------------------------------------------------------------------------
// k_merge: per (word, tree): cross-word horiz link + vertical overlap starts
// ---------------------------------------------------------------------------
__global__ void k_merge() {
    int i = blockIdx.x * blockDim.x + threadIdx.x;
    if (i >= 2 * NW) return;
    int w = (i >= NW) ? (i - NW) : i;
    int* par;
    unsigned int* bm;
    if (i >= NW) { par = g_parT; bm = g_bmT; }
    else         { par = g_parP; bm = g_bmP; }
    int base = w * 32;
    unsigned int c = bm[w];
    if (!c) return;
    if ((w & 31) && (c & 1u) && (bm[w - 1] >> 31)) unite(par, base, base - 1);
    int row = w >> 5;
    if (row & (HH - 1)) {                      // not first row of image
        unsigned int o = c & bm[w - 32];
        unsigned int s = o & ~(o << 1);
        while (s) {
            int k = __ffs(s) - 1; s &= s - 1;
            unite(par, base + k, base + k - WW);
        }
    }
}

// ---------------------------------------------------------------------------
// k_flag: per (word, tree): atomicOr sign bit on root of runs with mistakes
// ---------------------------------------------------------------------------
__global__ void k_flag() {
    int i = blockIdx.x * blockDim.x + threadIdx.x;
    if (i >= 2 * NW) return;
    int w = (i >= NW) ? (i - NW) : i;
    int* par;
    unsigned int bm, other;
    if (i >= NW) { par = g_parT; bm = g_bmT[w]; other = g_bmP[w]; }
    else         { par = g_parP; bm = g_bmP[w]; other = g_bmT[w]; }
    if (!bm) return;
    unsigned int mistake = bm & ~other;
    int base = w * 32;
    unsigned int runs = bm & ~(bm << 1);
    while (runs) {
        int s = __ffs(runs) - 1; runs &= runs - 1;
        unsigned int rest = (~bm) & (s == 31 ? 0x80000000u : (~0u << s));
        int e = rest ? (__ffs(rest) - 1) : 32;
        unsigned int runmask = ((e < 32 ? ((1u << e) - 1u) : ~0u)) & (~0u << s);
        if (mistake & runmask) {
            bool fl;
            int r = find_flag(par, base + s, &fl);
            if (!fl) atomicOr(&par[r], (int)0x80000000);
        }
    }
}

// ---------------------------------------------------------------------------
// k_weight: per (word, tree): one find per run, broadcast flag to run bits
// ---------------------------------------------------------------------------
__global__ void k_weight() {
    int i = blockIdx.x * blockDim.x + threadIdx.x;
    if (i >= 2 * NW) return;
    int w = (i >= NW) ? (i - NW) : i;
    int* par;
    unsigned int bm;
    unsigned int* out;
    if (i >= NW) { par = g_parT; bm = g_bmT[w]; out = g_wT; }
    else         { par = g_parP; bm = g_bmP[w]; out = g_wP; }
    unsigned int res = 0;
    if (bm) {
        int base = w * 32;
        unsigned int runs = bm & ~(bm << 1);
        while (runs) {
            int s = __ffs(runs) - 1; runs &= runs - 1;
            unsigned int rest = (~bm) & (s == 31 ? 0x80000000u : (~0u << s));
            int e = rest ? (__ffs(rest) - 1) : 32;
            unsigned int runmask = ((e < 32 ? ((1u << e) - 1u) : ~0u)) & (~0u << s);
            bool fl;
            find_flag(par, base + s, &fl);
            if (fl) res |= runmask;
        }
    }
    out[w] = res;
}

// ---------------------------------------------------------------------------
// k_final: pure streaming weighted BCE-with-logits + reduction
// weight = 0.5 + 0.25*wT_bit + 0.25*wP_bit
// ---------------------------------------------------------------------------
__global__ __launch_bounds__(256) void k_final(const float* __restrict__ preds,
                                               const float* __restrict__ targs) {
    int i = blockIdx.x * blockDim.x + threadIdx.x;   // vec8 index
    int base = i << 3;
    int w = base >> 5;                               // same word for all 8 px
    int b0 = base & 31;
    unsigned int wp = g_wP[w] >> b0;
    unsigned int wt = g_wT[w] >> b0;
    float local = 0.0f;
    const float4* P = reinterpret_cast<const float4*>(preds);
    const float4* T = reinterpret_cast<const float4*>(targs);
#pragma unroll
    for (int h = 0; h < 2; h++) {
        float4 p4 = P[2 * i + h];
        float4 t4 = T[2 * i + h];
        float pv[4] = {p4.x, p4.y, p4.z, p4.w};
        float tv[4] = {t4.x, t4.y, t4.z, t4.w};
#pragma unroll
        for (int j = 0; j < 4; j++) {
            float p = pv[j];
            float t = tv[j];
            float loss = fmaxf(p, 0.0f) - p * t + log1pf(expf(-fabsf(p)));
            int bit = 4 * h + j;
            float wgt = 0.5f + 0.25f * (float)((wt >> bit) & 1u)
                             + 0.25f * (float)((wp >> bit) & 1u);
            local += wgt * loss;
        }
    }
#pragma unroll
    for (int off = 16; off > 0; off >>= 1)
        local += __shfl_down_sync(0xffffffffu, local, off);
    __shared__ float ssum[8];
    int lane = threadIdx.x & 31;
    int warp = threadIdx.x >> 5;
    if (lane == 0) ssum[warp] = local;
    __syncthreads();
    if (warp == 0) {
        float v = (lane < (blockDim.x >> 5)) ? ssum[lane] : 0.0f;
#pragma unroll
        for (int off = 4; off > 0; off >>= 1)
            v += __shfl_down_sync(0xffffffffu, v, off);
        if (lane == 0) atomicAdd(&g_sum, (double)v);
    }
}

__global__ void k_out(float* __restrict__ out) {
    out[0] = (float)(g_sum / (double)NTOT);
}

// ---------------------------------------------------------------------------
extern "C" void kernel_launch(void* const* d_in, const int* in_sizes, int n_in,
                              void* d_out, int out_size) {
    const float* preds = (const float*)d_in[0];
    const float* targs = (const float*)d_in[1];
    float* out = (float*)d_out;

    k_init  <<<NTOT / 1024, 256>>>(preds, targs);
    k_merge <<<2 * NW / 256, 256>>>();
    k_flag  <<<2 * NW / 256, 256>>>();
    k_weight<<<2 * NW / 256, 256>>>();
    k_final <<<NTOT / 8 / 256, 256>>>(preds, targs);
    k_out   <<<1, 1>>>(out);
}

// round 5
// speedup vs baseline: 13.0950x; 1.2253x over previous
#include <cuda_runtime.h>
#include <math.h>

#define BATCH 16
#define HH 1024
#define WW 1024
#define NPIX (HH*WW)
#define NTOT (BATCH*NPIX)
#define NW   (NTOT/32)          // 524288 bitmap words
#define NODE (NW*16)            // <=16 runs per 32-bit word
#define MASK31 0x7fffffff

// Scratch (__device__ globals; no allocation)
__device__ int g_parP[NODE];
__device__ int g_parT[NODE];
__device__ unsigned int g_bmP[NW];
__device__ unsigned int g_bmT[NW];
__device__ unsigned int g_wP[NW];   // per-pixel component-flag bitmaps
__device__ unsigned int g_wT[NW];
__device__ double g_sum;

// ---------------------------------------------------------------------------
// k_pinit: identity parent init (data-independent, vectorized)
// ---------------------------------------------------------------------------
__global__ __launch_bounds__(256) void k_pinit() {
    int i = blockIdx.x * blockDim.x + threadIdx.x;   // int4 index
    int base = i << 2;
    int4 v = make_int4(base, base + 1, base + 2, base + 3);
    reinterpret_cast<int4*>(g_parP)[i] = v;
    reinterpret_cast<int4*>(g_parT)[i] = v;
    if (i == 0) g_sum = 0.0;
}

// ---------------------------------------------------------------------------
// k_init: build fg bitmaps only (one block = one 1024-px row)
// ---------------------------------------------------------------------------
__global__ __launch_bounds__(256) void k_init(const float* __restrict__ preds,
                                              const float* __restrict__ targs) {
    __shared__ unsigned char snP[256], snT[256];
    int t = threadIdx.x;
    int i4 = blockIdx.x * 256 + t;
    float4 p  = reinterpret_cast<const float4*>(preds)[i4];
    float4 tg = reinterpret_cast<const float4*>(targs)[i4];
    unsigned int nP = (unsigned int)(p.x  > 0.5f) | ((unsigned int)(p.y  > 0.5f) << 1)
                    | ((unsigned int)(p.z  > 0.5f) << 2) | ((unsigned int)(p.w  > 0.5f) << 3);
    unsigned int nT = (unsigned int)(tg.x > 0.0f) | ((unsigned int)(tg.y > 0.0f) << 1)
                    | ((unsigned int)(tg.z > 0.0f) << 2) | ((unsigned int)(tg.w > 0.0f) << 3);
    snP[t] = (unsigned char)nP;
    snT[t] = (unsigned char)nT;
    __syncthreads();
    if (t < 64) {
        int w = t >> 1;          // word within row (0..31)
        int half = t & 1;        // P or T
        const unsigned char* sn = half ? snT : snP;
        unsigned int word = 0;
#pragma unroll
        for (int j = 0; j < 8; j++)
            word |= ((unsigned int)sn[w * 8 + j]) << (4 * j);
        if (half) g_bmT[blockIdx.x * 32 + w] = word;
        else      g_bmP[blockIdx.x * 32 + w] = word;
    }
}

// ---------------------------------------------------------------------------
// union-find on run nodes
// ---------------------------------------------------------------------------
__device__ __forceinline__ int find_nc(int* par, int l) {
    int p = par[l];
    while (p != l) { l = p; p = par[l]; }
    return l;
}
__device__ __forceinline__ void unite(int* par, int a, int b) {
    while (true) {
        a = find_nc(par, a);
        b = find_nc(par, b);
        if (a == b) return;
        if (a < b) { int tmp = a; a = b; b = tmp; }   // a > b
        int old = atomicMin(&par[a], b);
        if (old == a) return;
        a = old;
    }
}
// post-merge find with path halving; returns root, sets *fl if root flagged.
__device__ __forceinline__ int find_flag(int* par, int l, bool* fl) {
    int p = par[l];
    int m = p & MASK31;
    while (m != l) {
        int p2 = par[m];
        int m2 = p2 & MASK31;
        if (m2 != m) par[l] = m2;
        l = m; p = p2; m = m2;
    }
    *fl = (p < 0);
    return l;
}

// ---------------------------------------------------------------------------
// k_merge: per (word, tree): cross-word horiz link + vertical overlap starts
// ---------------------------------------------------------------------------
__global__ void k_merge() {
    int i = blockIdx.x * blockDim.x + threadIdx.x;
    if (i >= 2 * NW) return;
    int w = (i >= NW) ? (i - NW) : i;
    int* par;
    unsigned int* bm;
    if (i >= NW) { par = g_parT; bm = g_bmT; }
    else         { par = g_parP; bm = g_bmP; }
    unsigned int c = bm[w];
    if (!c) return;
    unsigned int rs = c & ~(c << 1);           // run starts in this word
    int nbase = w * 16;
    if ((w & 31) && (c & 1u)) {
        unsigned int pc = bm[w - 1];
        if (pc >> 31) {
            unsigned int prs = pc & ~(pc << 1);
            unite(par, nbase, (w - 1) * 16 + __popc(prs) - 1);
        }
    }
    int row = w >> 5;
    if (row & (HH - 1)) {                      // not first row of image
        unsigned int u = bm[w - 32];
        unsigned int o = c & u;
        if (o) {
            unsigned int urs = u & ~(u << 1);
            unsigned int s = o & ~(o << 1);    // overlap-segment starts
            while (s) {
                int k = __ffs(s) - 1; s &= s - 1;
                unsigned int mk = ((1u << k) << 1) - 1u;   // bits 0..k
                int rc = __popc(rs & mk) - 1;
                int ru = __popc(urs & mk) - 1;
                unite(par, nbase + rc, (w - 32) * 16 + ru);
            }
        }
    }
}

// ---------------------------------------------------------------------------
// k_flag: per (word, tree): flag root (sign bit) of runs containing mistakes
// ---------------------------------------------------------------------------
__global__ void k_flag() {
    int i = blockIdx.x * blockDim.x + threadIdx.x;
    if (i >= 2 * NW) return;
    int w = (i >= NW) ? (i - NW) : i;
    int* par;
    unsigned int c, other;
    if (i >= NW) { par = g_parT; c = g_bmT[w]; other = g_bmP[w]; }
    else         { par = g_parP; c = g_bmP[w]; other = g_bmT[w]; }
    if (!c) return;
    unsigned int mistake = c & ~other;
    if (!mistake) return;
    unsigned int runs = c & ~(c << 1);
    int ridx = 0;
    while (runs) {
        int s = __ffs(runs) - 1; runs &= runs - 1;
        int e = runs ? (__ffs(runs) - 1) : 32;          // next run start
        unsigned int seg = (e < 32 ? ((1u << e) - 1u) : ~0u) & (~0u << s);
        if (mistake & seg) {
            bool fl;
            int r = find_flag(par, w * 16 + ridx, &fl);
            if (!fl) atomicOr(&par[r], (int)0x80000000);
        }
        ridx++;
    }
}

// ---------------------------------------------------------------------------
// k_weight: per (word, tree): one find per run, broadcast flag to run bits
// ---------------------------------------------------------------------------
__global__ void k_weight() {
    int i = blockIdx.x * blockDim.x + threadIdx.x;
    if (i >= 2 * NW) return;
    int w = (i >= NW) ? (i - NW) : i;
    int* par;
    unsigned int c;
    unsigned int* out;
    if (i >= NW) { par = g_parT; c = g_bmT[w]; out = g_wT; }
    else         { par = g_parP; c = g_bmP[w]; out = g_wP; }
    unsigned int res = 0;
    if (c) {
        unsigned int runs = c & ~(c << 1);
        int ridx = 0;
        while (runs) {
            int s = __ffs(runs) - 1; runs &= runs - 1;
            int e = runs ? (__ffs(runs) - 1) : 32;
            bool fl;
            find_flag(par, w * 16 + ridx, &fl);
            if (fl) res |= (e < 32 ? ((1u << e) - 1u) : ~0u) & (~0u << s);
            ridx++;
        }
        res &= c;    // clear bg gap bits
    }
    out[w] = res;
}

// ---------------------------------------------------------------------------
// k_final: pure streaming weighted BCE-with-logits + reduction
// weight = 0.5 + 0.25*wT_bit + 0.25*wP_bit
// ---------------------------------------------------------------------------
__global__ __launch_bounds__(256) void k_final(const float* __restrict__ preds,
                                               const float* __restrict__ targs) {
    int i = blockIdx.x * blockDim.x + threadIdx.x;   // vec8 index
    int base = i << 3;
    int w = base >> 5;
    int b0 = base & 31;
    unsigned int wp = g_wP[w] >> b0;
    unsigned int wt = g_wT[w] >> b0;
    float local = 0.0f;
    const float4* P = reinterpret_cast<const float4*>(preds);
    const float4* T = reinterpret_cast<const float4*>(targs);
#pragma unroll
    for (int h = 0; h < 2; h++) {
        float4 p4 = P[2 * i + h];
        float4 t4 = T[2 * i + h];
        float pv[4] = {p4.x, p4.y, p4.z, p4.w};
        float tv[4] = {t4.x, t4.y, t4.z, t4.w};
#pragma unroll
        for (int j = 0; j < 4; j++) {
            float p = pv[j];
            float t = tv[j];
            float loss = fmaxf(p, 0.0f) - p * t + log1pf(expf(-fabsf(p)));
            int bit = 4 * h + j;
            float wgt = 0.5f + 0.25f * (float)((wt >> bit) & 1u)
                             + 0.25f * (float)((wp >> bit) & 1u);
            local += wgt * loss;
        }
    }
#pragma unroll
    for (int off = 16; off > 0; off >>= 1)
        local += __shfl_down_sync(0xffffffffu, local, off);
    __shared__ float ssum[8];
    int lane = threadIdx.x & 31;
    int warp = threadIdx.x >> 5;
    if (lane == 0) ssum[warp] = local;
    __syncthreads();
    if (warp == 0) {
        float v = (lane < (blockDim.x >> 5)) ? ssum[lane] : 0.0f;
#pragma unroll
        for (int off = 4; off > 0; off >>= 1)
            v += __shfl_down_sync(0xffffffffu, v, off);
        if (lane == 0) atomicAdd(&g_sum, (double)v);
    }
}

__global__ void k_out(float* __restrict__ out) {
    out[0] = (float)(g_sum / (double)NTOT);
}

// ---------------------------------------------------------------------------
extern "C" void kernel_launch(void* const* d_in, const int* in_sizes, int n_in,
                              void* d_out, int out_size) {
    const float* preds = (const float*)d_in[0];
    const float* targs = (const float*)d_in[1];
    float* out = (float*)d_out;

    k_pinit <<<NODE / 4 / 256, 256>>>();
    k_init  <<<NTOT / 1024, 256>>>(preds, targs);
    k_merge <<<2 * NW / 256, 256>>>();
    k_flag  <<<2 * NW / 256, 256>>>();
    k_weight<<<2 * NW / 256, 256>>>();
    k_final <<<NTOT / 8 / 256, 256>>>(preds, targs);
    k_out   <<<1, 1>>>(out);
}

// round 7
// speedup vs baseline: 14.2275x; 1.0865x over previous
#include <cuda_runtime.h>
#include <cuda_fp16.h>
#include <math.h>

#define BATCH 16
#define HH 1024
#define WW 1024
#define NPIX (HH*WW)
#define NTOT (BATCH*NPIX)
#define NW   (NTOT/32)          // 524288 bitmap words
#define NODE (NW*16)            // <=16 runs per 32-bit word
#define MASK31 0x7fffffff

// Scratch (__device__ globals; no allocation)
__device__ int g_parP[NODE];
__device__ int g_parT[NODE];
__device__ unsigned int g_bmP[NW];
__device__ unsigned int g_bmT[NW];
__device__ __half2 g_loss[NTOT/2];  // fp16 per-pixel BCE loss (32 MB)
__device__ double g_sum;

// ---------------------------------------------------------------------------
__global__ void k_zero() { g_sum = 0.0; }

// ---------------------------------------------------------------------------
// k_init: bitmaps + fp16 loss + 0.5*sum(loss) + identity parent init
// one block = one 1024-px row
// ---------------------------------------------------------------------------
__global__ __launch_bounds__(256) void k_init(const float* __restrict__ preds,
                                              const float* __restrict__ targs) {
    __shared__ unsigned char snP[256], snT[256];
    __shared__ float ssum[8];
    int t = threadIdx.x;
    int i4 = blockIdx.x * 256 + t;
    float4 p  = reinterpret_cast<const float4*>(preds)[i4];
    float4 tg = reinterpret_cast<const float4*>(targs)[i4];
    unsigned int nP = (unsigned int)(p.x  > 0.5f) | ((unsigned int)(p.y  > 0.5f) << 1)
                    | ((unsigned int)(p.z  > 0.5f) << 2) | ((unsigned int)(p.w  > 0.5f) << 3);
    unsigned int nT = (unsigned int)(tg.x > 0.0f) | ((unsigned int)(tg.y > 0.0f) << 1)
                    | ((unsigned int)(tg.z > 0.0f) << 2) | ((unsigned int)(tg.w > 0.0f) << 3);
    snP[t] = (unsigned char)nP;
    snT[t] = (unsigned char)nT;

    // loss (f32), store fp16, accumulate f32
    float pv[4] = {p.x, p.y, p.z, p.w};
    float tv[4] = {tg.x, tg.y, tg.z, tg.w};
    float lv[4];
    float local = 0.0f;
#pragma unroll
    for (int j = 0; j < 4; j++) {
        float pp = pv[j];
        float l = fmaxf(pp, 0.0f) - pp * tv[j] + log1pf(expf(-fabsf(pp)));
        lv[j] = l;
        local += l;
    }
    __half2 h0 = __floats2half2_rn(lv[0], lv[1]);
    __half2 h1 = __floats2half2_rn(lv[2], lv[3]);
    uint2 packed;
    packed.x = *reinterpret_cast<unsigned int*>(&h0);
    packed.y = *reinterpret_cast<unsigned int*>(&h1);
    reinterpret_cast<uint2*>(g_loss)[i4] = packed;

    // identity parent init for this row's nodes (both trees)
    {
        int tree = t >> 7;
        int rem = t & 127;
        int wir = rem >> 2;     // word in row 0..31
        int q = rem & 3;
        int base = (blockIdx.x * 32 + wir) * 16 + q * 4;
        int4 v = make_int4(base, base + 1, base + 2, base + 3);
        if (tree) reinterpret_cast<int4*>(g_parT)[base >> 2] = v;
        else      reinterpret_cast<int4*>(g_parP)[base >> 2] = v;
    }
    __syncthreads();

    if (t < 64) {
        int w = t >> 1;
        int half = t & 1;
        const unsigned char* sn = half ? snT : snP;
        unsigned int word = 0;
#pragma unroll
        for (int j = 0; j < 8; j++)
            word |= ((unsigned int)sn[w * 8 + j]) << (4 * j);
        if (half) g_bmT[blockIdx.x * 32 + w] = word;
        else      g_bmP[blockIdx.x * 32 + w] = word;
    }

    // block reduce 0.5 * sum(loss)
#pragma unroll
    for (int off = 16; off > 0; off >>= 1)
        local += __shfl_down_sync(0xffffffffu, local, off);
    int lane = t & 31;
    int warp = t >> 5;
    if (lane == 0) ssum[warp] = local;
    __syncthreads();
    if (warp == 0) {
        float v = (lane < 8) ? ssum[lane] : 0.0f;
#pragma unroll
        for (int off = 4; off > 0; off >>= 1)
            v += __shfl_down_sync(0xffffffffu, v, off);
        if (lane == 0) atomicAdd(&g_sum, (double)(0.5f * v));
    }
}

// ---------------------------------------------------------------------------
// union-find on run nodes
// ---------------------------------------------------------------------------
__device__ __forceinline__ int find_nc(int* par, int l) {
    int p = par[l];
    while (p != l) { l = p; p = par[l]; }
    return l;
}
__device__ __forceinline__ void unite(int* par, int a, int b) {
    while (true) {
        a = find_nc(par, a);
        b = find_nc(par, b);
        if (a == b) return;
        if (a < b) { int tmp = a; a = b; b = tmp; }   // a > b
        int old = atomicMin(&par[a], b);
        if (old == a) return;
        a = old;
    }
}
// post-merge find with path halving; returns root, sets *fl if root flagged.
// halving writes only non-root slots with masked (flag-free) ancestors.
__device__ __forceinline__ int find_flag(int* par, int l, bool* fl) {
    int p = par[l];
    int m = p & MASK31;
    while (m != l) {
        int p2 = par[m];
        int m2 = p2 & MASK31;
        if (m2 != m) par[l] = m2;
        l = m; p = p2; m = m2;
    }
    *fl = (p < 0);
    return l;
}

// ---------------------------------------------------------------------------
// k_merge: per (word, tree): cross-word horiz link + vertical overlap starts
// ---------------------------------------------------------------------------
__global__ void k_merge() {
    int i = blockIdx.x * blockDim.x + threadIdx.x;
    if (i >= 2 * NW) return;
    int w = (i >= NW) ? (i - NW) : i;
    int* par;
    unsigned int* bm;
    if (i >= NW) { par = g_parT; bm = g_bmT; }
    else         { par = g_parP; bm = g_bmP; }
    unsigned int c = bm[w];
    if (!c) return;
    unsigned int rs = c & ~(c << 1);           // run starts in this word
    int nbase = w * 16;
    if ((w & 31) && (c & 1u)) {
        unsigned int pc = bm[w - 1];
        if (pc >> 31) {
            unsigned int prs = pc & ~(pc << 1);
            unite(par, nbase, (w - 1) * 16 + __popc(prs) - 1);
        }
    }
    int row = w >> 5;
    if (row & (HH - 1)) {                      // not first row of image
        unsigned int u = bm[w - 32];
        unsigned int o = c & u;
        if (o) {
            unsigned int urs = u & ~(u << 1);
            unsigned int s = o & ~(o << 1);    // overlap-segment starts
            while (s) {
                int k = __ffs(s) - 1; s &= s - 1;
                unsigned int mk = ((1u << k) << 1) - 1u;   // bits 0..k
                int rc = __popc(rs & mk) - 1;
                int ru = __popc(urs & mk) - 1;
                unite(par, nbase + rc, (w - 32) * 16 + ru);
            }
        }
    }
}

// ---------------------------------------------------------------------------
// k_flag: flag root (sign bit, idempotent plain store) of runs with mistakes
// ---------------------------------------------------------------------------
__global__ void k_flag() {
    int i = blockIdx.x * blockDim.x + threadIdx.x;
    if (i >= 2 * NW) return;
    int w = (i >= NW) ? (i - NW) : i;
    int* par;
    unsigned int c, other;
    if (i >= NW) { par = g_parT; c = g_bmT[w]; other = g_bmP[w]; }
    else         { par = g_parP; c = g_bmP[w]; other = g_bmT[w]; }
    if (!c) return;
    unsigned int mistake = c & ~other;
    if (!mistake) return;
    unsigned int runs = c & ~(c << 1);
    int ridx = 0;
    while (runs) {
        int s = __ffs(runs) - 1; runs &= runs - 1;
        int e = runs ? (__ffs(runs) - 1) : 32;          // next run start
        unsigned int seg = (e < 32 ? ((1u << e) - 1u) : ~0u) & (~0u << s);
        if (mistake & seg) {
            bool fl;
            int r = find_flag(par, w * 16 + ridx, &fl);
            if (!fl) par[r] = (int)(((unsigned int)r) | 0x80000000u);
        }
        ridx++;
    }
}

// ---------------------------------------------------------------------------
// k_fuse: per (word, tree): find per run -> flag bits -> 0.25*sum(flagged loss)
// ---------------------------------------------------------------------------
__global__ __launch_bounds__(256) void k_fuse() {
    int i = blockIdx.x * blockDim.x + threadIdx.x;
    int w = (i >= NW) ? (i - NW) : i;
    int* par;
    unsigned int c;
    if (i >= NW) { par = g_parT; c = g_bmT[w]; }
    else         { par = g_parP; c = g_bmP[w]; }
    float local = 0.0f;
    if (c) {
        unsigned int res = 0;
        unsigned int runs = c & ~(c << 1);
        int ridx = 0;
        while (runs) {
            int s = __ffs(runs) - 1; runs &= runs - 1;
            int e = runs ? (__ffs(runs) - 1) : 32;
            bool fl;
            find_flag(par, w * 16 + ridx, &fl);
            if (fl) res |= (e < 32 ? ((1u << e) - 1u) : ~0u) & (~0u << s);
            ridx++;
        }
        res &= c;
        if (res) {
            const uint4* L = reinterpret_cast<const uint4*>(g_loss) + w * 4;
            float sum = 0.0f;
#pragma unroll
            for (int q = 0; q < 4; q++) {
                uint4 v = L[q];
                unsigned int r8 = res >> (q * 8);
                unsigned int uu[4] = {v.x, v.y, v.z, v.w};
#pragma unroll
                for (int h = 0; h < 4; h++) {
                    unsigned int u = uu[h];
                    __half2 hh = *reinterpret_cast<__half2*>(&u);
                    float2 f = __half22float2(hh);
                    if (r8 & 1u) sum += f.x;
                    if (r8 & 2u) sum += f.y;
                    r8 >>= 2;
                }
            }
            local = 0.25f * sum;
        }
    }
#pragma unroll
    for (int off = 16; off > 0; off >>= 1)
        local += __shfl_down_sync(0xffffffffu, local, off);
    __shared__ float ssum[8];
    int lane = threadIdx.x & 31;
    int warp = threadIdx.x >> 5;
    if (lane == 0) ssum[warp] = local;
    __syncthreads();
    if (warp == 0) {
        float v = (lane < (blockDim.x >> 5)) ? ssum[lane] : 0.0f;
#pragma unroll
        for (int off = 4; off > 0; off >>= 1)
            v += __shfl_down_sync(0xffffffffu, v, off);
        if (lane == 0) atomicAdd(&g_sum, (double)v);
    }
}

__global__ void k_out(float* __restrict__ out) {
    out[0] = (float)(g_sum / (double)NTOT);
}

// ---------------------------------------------------------------------------
extern "C" void kernel_launch(void* const* d_in, const int* in_sizes, int n_in,
                              void* d_out, int out_size) {
    const float* preds = (const float*)d_in[0];
    const float* targs = (const float*)d_in[1];
    float* out = (float*)d_out;

    k_zero <<<1, 1>>>();
    k_init <<<NTOT / 1024, 256>>>(preds, targs);
    k_merge<<<2 * NW / 256, 256>>>();
    k_flag <<<2 * NW / 256, 256>>>();
    k_fuse <<<2 * NW / 256, 256>>>();
    k_out  <<<1, 1>>>(out);
}